// round 17
// baseline (speedup 1.0000x reference)
#include <cuda_runtime.h>
#include <cstdint>

#define BB 2
#define SQ 1024
#define SK 1024
#define DD 64
#define DV 64
#define NSPLIT 18
#define KFIX 32                // static slots per split
#define NCOV (NSPLIT * KFIX)   // 576 covered ranks
#define KB 8                   // keys per pipelined section
#define NPASS (KFIX / KB)      // 4
#define QPB 64
#define TPB 128
#define KPT (SK / TPB)         // 8 mask keys per thread
#define NTILE (SQ / QPB)       // 16
#define NTAIL 4

#define LOG2E 1.4426950408889634f
#define ABS2_MASK 0x7FFFFFFF7FFFFFFFULL
#define FULLM 0xffffffffu

typedef unsigned long long ull;

// partials: [b][split(18)][dp(32)][q(1024)]
__device__ ull   g_pacc[(size_t)BB * NSPLIT * (DV / 2) * SQ];
__device__ float g_pl[(size_t)BB * NSPLIT * SQ];
__device__ int   g_cnt[BB * NTILE];
__device__ int   g_fin[BB * NTILE];

__device__ __forceinline__ ull add_f32x2(ull a, ull b) {
    ull r;
    asm("add.rn.f32x2 %0, %1, %2;" : "=l"(r) : "l"(a), "l"(b));
    return r;
}
__device__ __forceinline__ ull fma_f32x2(ull a, ull b, ull c) {
    ull r;
    asm("fma.rn.f32x2 %0, %1, %2, %3;" : "=l"(r) : "l"(a), "l"(b), "l"(c));
    return r;
}
__device__ __forceinline__ ull pack_dup(float p) {
    ull r;
    asm("mov.b64 %0, {%1, %1};" : "=l"(r) : "r"(__float_as_uint(p)));
    return r;
}
__device__ __forceinline__ float ex2(float x) {
    float r;
    asm("ex2.approx.f32 %0, %1;" : "=f"(r) : "f"(x));
    return r;
}

// dual-query L1 over 16 dims: 4 shared LDS.128, 2 chains per query
__device__ __forceinline__ float2 l1_16x2(const ulonglong2* __restrict__ kp,
                                          const ull* __restrict__ qa,
                                          const ull* __restrict__ qb)
{
    ulonglong2 k0 = kp[0];
    ulonglong2 k1 = kp[1];
    ulonglong2 k2 = kp[2];
    ulonglong2 k3 = kp[3];
    ull a0 = add_f32x2(k0.x, qa[0]) & ABS2_MASK;
    ull b0 = add_f32x2(k0.x, qb[0]) & ABS2_MASK;
    ull a1 = add_f32x2(k0.y, qa[1]) & ABS2_MASK;
    ull b1 = add_f32x2(k0.y, qb[1]) & ABS2_MASK;
    a0 = add_f32x2(a0, add_f32x2(k1.x, qa[2]) & ABS2_MASK);
    b0 = add_f32x2(b0, add_f32x2(k1.x, qb[2]) & ABS2_MASK);
    a1 = add_f32x2(a1, add_f32x2(k1.y, qa[3]) & ABS2_MASK);
    b1 = add_f32x2(b1, add_f32x2(k1.y, qb[3]) & ABS2_MASK);
    a0 = add_f32x2(a0, add_f32x2(k2.x, qa[4]) & ABS2_MASK);
    b0 = add_f32x2(b0, add_f32x2(k2.x, qb[4]) & ABS2_MASK);
    a1 = add_f32x2(a1, add_f32x2(k2.y, qa[5]) & ABS2_MASK);
    b1 = add_f32x2(b1, add_f32x2(k2.y, qb[5]) & ABS2_MASK);
    a0 = add_f32x2(a0, add_f32x2(k3.x, qa[6]) & ABS2_MASK);
    b0 = add_f32x2(b0, add_f32x2(k3.x, qb[6]) & ABS2_MASK);
    a1 = add_f32x2(a1, add_f32x2(k3.y, qa[7]) & ABS2_MASK);
    b1 = add_f32x2(b1, add_f32x2(k3.y, qb[7]) & ABS2_MASK);
    a0 = add_f32x2(a0, a1);
    b0 = add_f32x2(b0, b1);
    float2 fa = *(float2*)&a0;
    float2 fb = *(float2*)&b0;
    return make_float2(fa.x + fa.y, fb.x + fb.y);
}

__global__ __launch_bounds__(TPB, 4)
void attn_fused(const float* __restrict__ q, const float* __restrict__ k,
                const float* __restrict__ v, const int* __restrict__ mask,
                float* __restrict__ out)
{
    const int b    = blockIdx.z;
    const int sg   = blockIdx.y;          // split 0..17
    const int qt   = blockIdx.x;          // q tile 0..15
    const int tid  = threadIdx.x;
    const int wd   = tid >> 5;            // warp = dim quarter
    const int ln   = tid & 31;            // query pair: qA=ln, qB=ln+32
    const int h    = tid >> 6;
    const int qloc = tid & 63;
    const int qi   = qt * QPB + qloc;
    const int qiA  = qt * QPB + ln;
    const int qiB  = qiA + 32;

    __shared__ __align__(16) float ks[KFIX][DD];           // 8KB
    __shared__ __align__(16) float vs[KFIX][DV];           // 8KB
    __shared__ __align__(16) float hbuf[2][KB][4][QPB];    // 16KB double-buffered
    __shared__ __align__(16) float k0s[DD];
    __shared__ __align__(16) float d0q[4][QPB];            // 1KB
    __shared__ int   inv_s[SK];                            // 4KB
    __shared__ int   wtot[4];
    __shared__ float bias[KFIX];
    __shared__ int   rank_s;

    // ---- in-block compaction scan (proven R15/R16) ----
    int nc;
    {
        const int4* mb = (const int4*)(mask + (size_t)b * SK);
        int4 a4 = mb[2 * tid];
        int4 b4 = mb[2 * tid + 1];
        int mv[KPT] = {a4.x, a4.y, a4.z, a4.w, b4.x, b4.y, b4.z, b4.w};
        int pre[KPT];
        int tsum = 0;
#pragma unroll
        for (int i = 0; i < KPT; i++) { pre[i] = tsum; tsum += (mv[i] ? 1 : 0); }
        int ws = tsum;
#pragma unroll
        for (int off = 1; off < 32; off <<= 1) {
            int t = __shfl_up_sync(FULLM, ws, off);
            if (ln >= off) ws += t;
        }
        if (ln == 31) wtot[wd] = ws;
        __syncthreads();
        int base = 0;
#pragma unroll
        for (int w = 0; w < 4; w++) base += (w < wd) ? wtot[w] : 0;
        int ex = base + ws - tsum;
#pragma unroll
        for (int i = 0; i < KPT; i++)
            if (mv[i]) inv_s[ex + pre[i]] = KPT * tid + i;
        nc = wtot[0] + wtot[1] + wtot[2] + wtot[3];
    }
    __syncthreads();

    const int ncl   = nc < NCOV ? nc : NCOV;
    const int start = (ncl * sg) / NSPLIT;
    const int cnt   = (ncl * (sg + 1)) / NSPLIT - start;   // <= KFIX

    // ---- gather this split's rows global->smem; zero pads; bias ----
    {
        for (int j = wd; j < cnt; j += 4) {
            int src = inv_s[start + j];
            float2 kk = ((const float2*)(k + ((size_t)b * SK + src) * DD))[ln];
            ((float2*)&ks[j][0])[ln] = kk;
            float2 vv = ((const float2*)(v + ((size_t)b * SK + src) * DV))[ln];
            ((float2*)&vs[j][0])[ln] = vv;
        }
        for (int j = cnt + wd; j < KFIX; j += 4) {
            ((float2*)&ks[j][0])[ln] = make_float2(0.0f, 0.0f);
            ((float2*)&vs[j][0])[ln] = make_float2(0.0f, 0.0f);
        }
        if (tid < KFIX)
            bias[tid] = (tid < cnt) ? 0.0f : 1e9f;
        if (tid < DD / 4)
            ((float4*)k0s)[tid] = ((const float4*)(k + (size_t)b * SK * DD))[tid];
    }

    // negated q quarters (dims [16wd, 16wd+16)) for both queries
    ull qnA[8], qnB[8];
    {
        const float* qra = q + ((size_t)b * SQ + qiA) * DD + 16 * wd;
        const float* qrb = q + ((size_t)b * SQ + qiB) * DD + 16 * wd;
#pragma unroll
        for (int i = 0; i < 4; i++) {
            float4 t = ((const float4*)qra)[i];
            float2 x = make_float2(-t.x, -t.y);
            float2 y = make_float2(-t.z, -t.w);
            qnA[2 * i]     = *(ull*)&x;
            qnA[2 * i + 1] = *(ull*)&y;
            float4 u = ((const float4*)qrb)[i];
            float2 z = make_float2(-u.x, -u.y);
            float2 w2 = make_float2(-u.z, -u.w);
            qnB[2 * i]     = *(ull*)&z;
            qnB[2 * i + 1] = *(ull*)&w2;
        }
    }
    __syncthreads();

    // reference distances: quarter partials -> d0q -> per-thread d0l2A/B
    {
        float2 dq = l1_16x2((const ulonglong2*)(k0s + 16 * wd), qnA, qnB);
        d0q[wd][ln]      = dq.x;
        d0q[wd][ln + 32] = dq.y;
    }
    __syncthreads();
    const float d0l2A = (d0q[0][ln] + d0q[1][ln] +
                         d0q[2][ln] + d0q[3][ln]) * LOG2E;
    const float d0l2B = (d0q[0][ln + 32] + d0q[1][ln + 32] +
                         d0q[2][ln + 32] + d0q[3][ln + 32]) * LOG2E;

    ull accA[8], accB[8];
#pragma unroll
    for (int i = 0; i < 8; i++) { accA[i] = 0ULL; accB[i] = 0ULL; }
    float lsumA = 0.0f, lsumB = 0.0f;

    // ---- prologue: 1a for first sub-block -> hbuf[0] ----
#pragma unroll
    for (int j = 0; j < KB; j++) {
        float2 dq = l1_16x2((const ulonglong2*)&ks[j][16 * wd], qnA, qnB);
        hbuf[0][j][wd][ln]      = dq.x;
        hbuf[0][j][wd][ln + 32] = dq.y;
    }
    __syncthreads();

    // ---- pipelined mainloop: phase2(cur) interleaved with 1a(next) ----
#pragma unroll
    for (int pass = 0; pass < NPASS; pass++) {
        const int cur = pass & 1;
        const int nxt = cur ^ 1;
        const int jb  = pass * KB;
#pragma unroll
        for (int j = 0; j < KB; j++) {
            if (pass < NPASS - 1) {
                float2 dq = l1_16x2(
                    (const ulonglong2*)&ks[jb + KB + j][16 * wd], qnA, qnB);
                hbuf[nxt][j][wd][ln]      = dq.x;
                hbuf[nxt][j][wd][ln + 32] = dq.y;
            }
            float bj = bias[jb + j];
            float dA = hbuf[cur][j][0][ln] + hbuf[cur][j][1][ln] +
                       hbuf[cur][j][2][ln] + hbuf[cur][j][3][ln] + bj;
            float dB = hbuf[cur][j][0][ln + 32] + hbuf[cur][j][1][ln + 32] +
                       hbuf[cur][j][2][ln + 32] + hbuf[cur][j][3][ln + 32] + bj;
            float pA = ex2(fmaf(dA, -LOG2E, d0l2A));
            float pB = ex2(fmaf(dB, -LOG2E, d0l2B));
            lsumA += pA;
            lsumB += pB;
            ull ppA = pack_dup(pA);
            ull ppB = pack_dup(pB);
            const ulonglong2* vp = (const ulonglong2*)&vs[jb + j][16 * wd];
            ulonglong2 v0 = vp[0];
            ulonglong2 v1 = vp[1];
            ulonglong2 v2 = vp[2];
            ulonglong2 v3 = vp[3];
            accA[0] = fma_f32x2(v0.x, ppA, accA[0]);
            accB[0] = fma_f32x2(v0.x, ppB, accB[0]);
            accA[1] = fma_f32x2(v0.y, ppA, accA[1]);
            accB[1] = fma_f32x2(v0.y, ppB, accB[1]);
            accA[2] = fma_f32x2(v1.x, ppA, accA[2]);
            accB[2] = fma_f32x2(v1.x, ppB, accB[2]);
            accA[3] = fma_f32x2(v1.y, ppA, accA[3]);
            accB[3] = fma_f32x2(v1.y, ppB, accB[3]);
            accA[4] = fma_f32x2(v2.x, ppA, accA[4]);
            accB[4] = fma_f32x2(v2.x, ppB, accB[4]);
            accA[5] = fma_f32x2(v2.y, ppA, accA[5]);
            accB[5] = fma_f32x2(v2.y, ppB, accB[5]);
            accA[6] = fma_f32x2(v3.x, ppA, accA[6]);
            accB[6] = fma_f32x2(v3.x, ppB, accB[6]);
            accA[7] = fma_f32x2(v3.y, ppA, accA[7]);
            accB[7] = fma_f32x2(v3.y, ppB, accB[7]);
        }
        __syncthreads();
    }

    // ---- cold overflow path (nc > NCOV; never hot for this input) ----
    if (sg == NSPLIT - 1 && nc > NCOV) {
        for (int j0 = NCOV; j0 < nc; j0++) {
            int src = inv_s[j0];
            float2 dq = l1_16x2(
                (const ulonglong2*)(k + ((size_t)b * SK + src) * DD + 16 * wd),
                qnA, qnB);
            hbuf[0][0][wd][ln]      = dq.x;
            hbuf[0][0][wd][ln + 32] = dq.y;
            __syncthreads();
            float dA = hbuf[0][0][0][ln] + hbuf[0][0][1][ln] +
                       hbuf[0][0][2][ln] + hbuf[0][0][3][ln];
            float dB = hbuf[0][0][0][ln + 32] + hbuf[0][0][1][ln + 32] +
                       hbuf[0][0][2][ln + 32] + hbuf[0][0][3][ln + 32];
            float pA = ex2(fmaf(dA, -LOG2E, d0l2A));
            float pB = ex2(fmaf(dB, -LOG2E, d0l2B));
            lsumA += pA;
            lsumB += pB;
            ull ppA = pack_dup(pA);
            ull ppB = pack_dup(pB);
            const ulonglong2* vp =
                (const ulonglong2*)(v + ((size_t)b * SK + src) * DV + 16 * wd);
#pragma unroll
            for (int i = 0; i < 4; i++) {
                ulonglong2 vv = vp[i];
                accA[2 * i]     = fma_f32x2(vv.x, ppA, accA[2 * i]);
                accB[2 * i]     = fma_f32x2(vv.x, ppB, accB[2 * i]);
                accA[2 * i + 1] = fma_f32x2(vv.y, ppA, accA[2 * i + 1]);
                accB[2 * i + 1] = fma_f32x2(vv.y, ppB, accB[2 * i + 1]);
            }
            __syncthreads();
        }
    }

    // ---- store partials + denominators ----
    {
        ull* pb = g_pacc + ((size_t)(b * NSPLIT + sg) * (DV / 2)) * SQ;
#pragma unroll
        for (int i = 0; i < 8; i++) {
            pb[(size_t)(8 * wd + i) * SQ + qiA] = accA[i];
            pb[(size_t)(8 * wd + i) * SQ + qiB] = accB[i];
        }
        if (wd == 0) {
            float* pl = g_pl + (size_t)(b * NSPLIT + sg) * SQ;
            pl[qiA] = lsumA;
            pl[qiB] = lsumB;
        }
    }

    // ---- arrival ticket: last NTAIL blocks per (b, qtile) combine ----
    const int tile = b * NTILE + qt;
    __threadfence();
    __syncthreads();
    if (tid == 0) rank_s = atomicAdd(&g_cnt[tile], 1);
    __syncthreads();
    const int c = rank_s;
    if (c < NSPLIT - NTAIL) return;

    if (tid == 0) {
        while (*(volatile int*)&g_cnt[tile] < NSPLIT) { }
    }
    __syncthreads();
    __threadfence();

    const int r = c - (NSPLIT - NTAIL);      // 0..3 -> dp slice [8r, 8r+8)

    float lt = 0.0f;
#pragma unroll
    for (int s2 = 0; s2 < NSPLIT; s2++)
        lt += g_pl[(size_t)(b * NSPLIT + s2) * SQ + qi];
    const float li = 1.0f / lt;

    const int dpb = r * 8 + h * 4;
    ull a[4] = {0ULL, 0ULL, 0ULL, 0ULL};
#pragma unroll
    for (int s2 = 0; s2 < NSPLIT; s2++) {
        const ull* base = g_pacc + ((size_t)(b * NSPLIT + s2) * (DV / 2)) * SQ + qi;
#pragma unroll
        for (int i = 0; i < 4; i++)
            a[i] = add_f32x2(a[i], base[(size_t)(dpb + i) * SQ]);
    }
#pragma unroll
    for (int i = 0; i < 4; i++) {
        float2 f = *(float2*)&a[i];
        float2 rr = make_float2(f.x * li, f.y * li);
        *(float2*)&out[((size_t)b * SQ + qi) * DV + 2 * (dpb + i)] = rr;
    }

    __threadfence();
    __syncthreads();
    if (tid == 0) {
        int f = atomicAdd(&g_fin[tile], 1);
        if (f == NTAIL - 1) {
            g_cnt[tile] = 0;
            g_fin[tile] = 0;
            __threadfence();
        }
    }
}

extern "C" void kernel_launch(void* const* d_in, const int* in_sizes, int n_in,
                              void* d_out, int out_size)
{
    const float* q    = (const float*)d_in[0];
    const float* k    = (const float*)d_in[1];
    const float* v    = (const float*)d_in[2];
    const int*   mask = (const int*)d_in[3];
    float* out = (float*)d_out;

    dim3 grid(NTILE, NSPLIT, BB);
    attn_fused<<<grid, TPB>>>(q, k, v, mask, out);
}